// round 1
// baseline (speedup 1.0000x reference)
#include <cuda_runtime.h>

#define B_ 32
#define S_ 4
#define L_ 64
#define C_ 32
#define H_ 4
#define D_ 8
#define CP_ 16

__device__ float g_xbuf[B_*S_*L_*C_];   // post-attn LN'd x
__device__ float g_mbuf[B_*L_*C_];      // max over tracks

// ---------------------------------------------------------------------------
// Kernel A: one block per (b,s). MSA build + LN -> QKV -> attention(+bulk bias)
// -> gate -> wo -> residual LN. 256 threads.
// ---------------------------------------------------------------------------
__global__ void __launch_bounds__(256) kA(
    const float* __restrict__ chip0, const float* __restrict__ chip1,
    const float* __restrict__ chip2, const float* __restrict__ chip3,
    const float* __restrict__ bulk,
    const float* __restrict__ we_w, const float* __restrict__ we_b,
    const float* __restrict__ pos,
    const float* __restrict__ mn_g, const float* __restrict__ mn_b,
    const float* __restrict__ wq, const float* __restrict__ bq,
    const float* __restrict__ wk, const float* __restrict__ bk,
    const float* __restrict__ wv, const float* __restrict__ bv,
    const float* __restrict__ wo, const float* __restrict__ bo,
    const float* __restrict__ an_g, const float* __restrict__ an_b,
    const float* __restrict__ conv_w, const float* __restrict__ conv_b,
    const float* __restrict__ gate_w, const float* __restrict__ gate_b)
{
    __shared__ float xs[L_][C_+1];
    __shared__ float qs[L_][C_+1];     // reused as attn-out after attention
    __shared__ float ks[L_][C_+1];
    __shared__ float vs[L_][C_+1];
    __shared__ float wsq[C_][C_+1], wsk[C_][C_+1], wsv[C_][C_+1];

    const int t = threadIdx.x;
    const int bs = blockIdx.x;
    const int b = bs >> 2, s = bs & 3;
    const float* chip = (s==0)?chip0:(s==1)?chip1:(s==2)?chip2:chip3;

    // stage QKV weights in smem (padded -> conflict-free reads)
    for (int idx = t; idx < C_*C_; idx += 256) {
        int r = idx >> 5, c = idx & 31;
        wsq[r][c] = wq[idx]; wsk[r][c] = wk[idx]; wsv[r][c] = wv[idx];
    }

    // phase 1: msa = sig*we_w + we_b + pos ; LN(mn) -> xs
    if (t < L_) {
        const int l = t;
        const float sig = chip[b*L_ + l];
        float vals[C_];
        float mean = 0.f;
        #pragma unroll
        for (int c = 0; c < C_; c++) {
            float v = sig * we_w[c] + we_b[c] + pos[l*C_ + c];
            vals[c] = v; mean += v;
        }
        mean *= (1.f/C_);
        float var = 0.f;
        #pragma unroll
        for (int c = 0; c < C_; c++) { float d = vals[c]-mean; var += d*d; }
        var *= (1.f/C_);
        const float rstd = rsqrtf(var + 1e-5f);
        #pragma unroll
        for (int c = 0; c < C_; c++)
            xs[l][c] = (vals[c]-mean)*rstd*mn_g[c] + mn_b[c];
    }
    __syncthreads();

    // phase 2: q,k,v projections
    for (int idx = t; idx < L_*C_; idx += 256) {
        const int l = idx >> 5, co = idx & 31;
        float aq = bq[co], ak = bk[co], av = bv[co];
        #pragma unroll
        for (int c = 0; c < C_; c++) {
            const float xv = xs[l][c];
            aq += xv * wsq[co][c];
            ak += xv * wsk[co][c];
            av += xv * wsv[co][c];
        }
        qs[l][co] = aq; ks[l][co] = ak; vs[l][co] = av;
    }
    __syncthreads();

    // phase 3: attention, thread = (h,l) — exactly 256 threads
    {
        const int h = t >> 6, l = t & 63;
        float qv[D_];
        #pragma unroll
        for (int d = 0; d < D_; d++) qv[d] = qs[l][h*D_+d];
        const float cw = conv_w[h], cb = conv_b[h];
        const float* brow = bulk + b*L_*L_ + l*L_;
        const float rsd = 0.35355339059327373f;  // 1/sqrt(8)

        float M = -1e30f, Z = 0.f;
        float acc[D_];
        #pragma unroll
        for (int d = 0; d < D_; d++) acc[d] = 0.f;

        for (int m = 0; m < L_; m++) {
            float sc = 0.f;
            #pragma unroll
            for (int d = 0; d < D_; d++) sc += qv[d]*ks[m][h*D_+d];
            sc = sc*rsd + brow[m]*cw + cb;
            if (sc > M) {
                const float scale = __expf(M - sc);
                Z *= scale;
                #pragma unroll
                for (int d = 0; d < D_; d++) acc[d] *= scale;
                M = sc;
            }
            const float p = __expf(sc - M);
            Z += p;
            #pragma unroll
            for (int d = 0; d < D_; d++) acc[d] += p * vs[m][h*D_+d];
        }
        const float inv = 1.f/Z;
        float o[D_];
        #pragma unroll
        for (int d = 0; d < D_; d++) o[d] = acc[d]*inv;

        // gate: sigmoid(gate_w[h] @ o + gate_b[h]) elementwise
        float og[D_];
        #pragma unroll
        for (int d = 0; d < D_; d++) {
            float g = gate_b[h*D_ + d];
            #pragma unroll
            for (int dd = 0; dd < D_; dd++)
                g += gate_w[h*D_*D_ + d*D_ + dd] * o[dd];
            og[d] = o[d] / (1.f + __expf(-g));
        }
        __syncthreads();           // all reads of qs done
        #pragma unroll
        for (int d = 0; d < D_; d++) qs[l][h*D_+d] = og[d];   // qs := attn out
    }
    __syncthreads();

    // phase 4: wo projection + residual + LN(an) -> global xbuf
    if (t < L_) {
        const int l = t;
        float vals[C_];
        float mean = 0.f;
        #pragma unroll
        for (int co = 0; co < C_; co++) {
            float a = bo[co];
            #pragma unroll
            for (int c = 0; c < C_; c++) a += qs[l][c]*wo[co*C_ + c];
            const float v = xs[l][co] + a;
            vals[co] = v; mean += v;
        }
        mean *= (1.f/C_);
        float var = 0.f;
        #pragma unroll
        for (int co = 0; co < C_; co++) { float d = vals[co]-mean; var += d*d; }
        var *= (1.f/C_);
        const float rstd = rsqrtf(var + 1e-5f);
        float* dst = g_xbuf + ((b*S_ + s)*L_ + l)*C_;
        #pragma unroll
        for (int co = 0; co < C_; co++)
            dst[co] = (vals[co]-mean)*rstd*an_g[co] + an_b[co];
    }
}

// ---------------------------------------------------------------------------
// Kernel A2: m[b,l,c] = max over tracks s
// ---------------------------------------------------------------------------
__global__ void kMax() {
    const int idx = blockIdx.x*256 + threadIdx.x;
    if (idx < B_*L_*C_) {
        const int b = idx / (L_*C_);
        const int lc = idx - b*(L_*C_);
        float m = g_xbuf[(b*S_)*L_*C_ + lc];
        #pragma unroll
        for (int s = 1; s < S_; s++)
            m = fmaxf(m, g_xbuf[(b*S_ + s)*L_*C_ + lc]);
        g_mbuf[idx] = m;
    }
}

// ---------------------------------------------------------------------------
// Kernel B: one block per (b,i). Uses the factorization
//   feat[b,i,j,p] = (m_i^T W_p m_j) / max(|m_i||m_j|,1e-6) + pp_b[p]
// then AdaNorm over p + SiLU, write transposed (B,CP,L,L).
// ---------------------------------------------------------------------------
__global__ void __launch_bounds__(256) kB(
    const float* __restrict__ pp_w, const float* __restrict__ pp_b,
    const float* __restrict__ ada_g, const float* __restrict__ ada_b,
    const float* __restrict__ ada_alpha, float* __restrict__ out)
{
    __shared__ float ms[L_][C_+1];
    __shared__ float wi[CP_][C_+1];
    __shared__ float feat[L_][CP_+1];
    __shared__ float nrm[L_], mu[L_], rs[L_];

    const int t = threadIdx.x;
    const int b = blockIdx.x >> 6, i = blockIdx.x & 63;
    const float* mb = g_mbuf + b*L_*C_;

    for (int idx = t; idx < L_*C_; idx += 256)
        ms[idx>>5][idx&31] = mb[idx];
    __syncthreads();

    if (t < L_) {
        float ssum = 0.f;
        #pragma unroll
        for (int c = 0; c < C_; c++) { const float v = ms[t][c]; ssum += v*v; }
        nrm[t] = sqrtf(ssum);
    }
    // wi[p][d] = sum_c m_i[c] * pp_w[p, c*C + d]   (m_i broadcast from smem)
    for (int idx = t; idx < CP_*C_; idx += 256) {
        const int p = idx >> 5, d = idx & 31;
        float a = 0.f;
        #pragma unroll
        for (int c = 0; c < C_; c++) a += ms[i][c] * pp_w[p*C_*C_ + c*C_ + d];
        wi[p][d] = a;
    }
    __syncthreads();

    const float ni = nrm[i];
    for (int idx = t; idx < L_*CP_; idx += 256) {
        const int p = idx >> 6, j = idx & 63;
        float a = 0.f;
        #pragma unroll
        for (int d = 0; d < C_; d++) a += wi[p][d]*ms[j][d];
        const float denom = fmaxf(ni*nrm[j], 1e-6f);
        feat[j][p] = a/denom + pp_b[p];
    }
    __syncthreads();

    if (t < L_) {
        float mean = 0.f;
        #pragma unroll
        for (int p = 0; p < CP_; p++) mean += feat[t][p];
        mean *= (1.f/CP_);
        float var = 0.f;
        #pragma unroll
        for (int p = 0; p < CP_; p++) { const float d = feat[t][p]-mean; var += d*d; }
        var *= (1.f/CP_);
        mu[t] = mean; rs[t] = rsqrtf(var + 1e-5f);
    }
    __syncthreads();

    const float alpha = ada_alpha[0];
    for (int idx = t; idx < L_*CP_; idx += 256) {
        const int p = idx >> 6, j = idx & 63;
        const float v = feat[j][p];
        const float ln = (v - mu[j])*rs[j]*ada_g[p] + ada_b[p];
        const float val = v + alpha*ln;
        const float r = val / (1.f + __expf(-val));
        out[((b*CP_ + p)*L_ + i)*L_ + j] = r;   // contiguous in j -> coalesced
    }
}

extern "C" void kernel_launch(void* const* d_in, const int* in_sizes, int n_in,
                              void* d_out, int out_size) {
    const float* in[29];
    for (int i = 0; i < 29 && i < n_in; i++) in[i] = (const float*)d_in[i];

    kA<<<B_*S_, 256>>>(in[0], in[1], in[2], in[3], in[4],
                       in[5], in[6], in[7], in[8], in[9],
                       in[10], in[11], in[12], in[13], in[14], in[15],
                       in[16], in[17], in[18], in[19],
                       in[20], in[21], in[22], in[23]);
    kMax<<<(B_*L_*C_ + 255)/256, 256>>>();
    kB<<<B_*L_, 256>>>(in[24], in[25], in[26], in[27], in[28], (float*)d_out);
}

// round 2
// speedup vs baseline: 1.0769x; 1.0769x over previous
#include <cuda_runtime.h>

#define B_ 32
#define S_ 4
#define L_ 64
#define C_ 32
#define H_ 4
#define D_ 8
#define CP_ 16

__device__ float g_xbuf[B_*S_*L_*C_];          // post-attn LN'd x
__device__ float g_mbuf[B_*L_*C_];             // max over tracks
__device__ float g_wibuf[B_*L_*CP_*C_];        // wi[b,i,p,d] = m_i^T W_p

// ---------------------------------------------------------------------------
// Kernel A: one block per (b,s). Dynamic smem (~66KB).
// Layout (floats):
//   xs   [64][33]  @0        qs [64][33] @2112
//   ks   [64][33]  @4224     vs [64][33] @6336
//   wsq  [32][33]  @8448     wsk @9504   wsv @10560  wso @11616
//   bulkS[64][65]  @12672    (total 16832 floats = 67328 B)
// ---------------------------------------------------------------------------
#define XS(l,c)  sm[(l)*33+(c)]
#define QS(l,c)  sm[2112+(l)*33+(c)]
#define KS(l,c)  sm[4224+(l)*33+(c)]
#define VS(l,c)  sm[6336+(l)*33+(c)]
#define WQ(r,c)  sm[8448+(r)*33+(c)]
#define WK(r,c)  sm[9504+(r)*33+(c)]
#define WV(r,c)  sm[10560+(r)*33+(c)]
#define WO(r,c)  sm[11616+(r)*33+(c)]
#define BK(l,m)  sm[12672+(l)*65+(m)]
#define KA_SMEM  (16832*4)

__global__ void __launch_bounds__(256) kA(
    const float* __restrict__ chip0, const float* __restrict__ chip1,
    const float* __restrict__ chip2, const float* __restrict__ chip3,
    const float* __restrict__ bulk,
    const float* __restrict__ we_w, const float* __restrict__ we_b,
    const float* __restrict__ pos,
    const float* __restrict__ mn_g, const float* __restrict__ mn_b,
    const float* __restrict__ wq, const float* __restrict__ bq,
    const float* __restrict__ wk, const float* __restrict__ bk,
    const float* __restrict__ wv, const float* __restrict__ bv,
    const float* __restrict__ wo, const float* __restrict__ bo,
    const float* __restrict__ an_g, const float* __restrict__ an_b,
    const float* __restrict__ conv_w, const float* __restrict__ conv_b,
    const float* __restrict__ gate_w, const float* __restrict__ gate_b)
{
    extern __shared__ float sm[];
    const int t = threadIdx.x;
    const int bs = blockIdx.x;
    const int b = bs >> 2, s = bs & 3;
    const float* chip = (s==0)?chip0:(s==1)?chip1:(s==2)?chip2:chip3;

    // stage weights (coalesced)
    for (int idx = t; idx < C_*C_; idx += 256) {
        const int r = idx >> 5, c = idx & 31;
        WQ(r,c) = wq[idx]; WK(r,c) = wk[idx]; WV(r,c) = wv[idx]; WO(r,c) = wo[idx];
    }
    // stage bulk row-block (coalesced; avoids 32-line gathers in the attn loop)
    for (int idx = t; idx < L_*L_; idx += 256)
        BK(idx>>6, idx&63) = bulk[b*L_*L_ + idx];

    // phase 1: msa + pos, LN(mn). Quad-parallel: 4 threads per row.
    {
        const int l = t >> 2, q = t & 3;
        const float sig = chip[b*L_ + l];
        float v[8]; float s1 = 0.f, s2 = 0.f;
        #pragma unroll
        for (int j = 0; j < 8; j++) {
            const int c = q*8 + j;
            const float val = sig*we_w[c] + we_b[c] + pos[l*C_ + c];
            v[j] = val; s1 += val; s2 += val*val;
        }
        s1 += __shfl_xor_sync(0xffffffffu, s1, 1); s1 += __shfl_xor_sync(0xffffffffu, s1, 2);
        s2 += __shfl_xor_sync(0xffffffffu, s2, 1); s2 += __shfl_xor_sync(0xffffffffu, s2, 2);
        const float mean = s1*(1.f/C_);
        const float var  = s2*(1.f/C_) - mean*mean;
        const float rstd = rsqrtf(var + 1e-5f);
        #pragma unroll
        for (int j = 0; j < 8; j++) {
            const int c = q*8 + j;
            XS(l,c) = (v[j]-mean)*rstd*mn_g[c] + mn_b[c];
        }
    }
    __syncthreads();

    // phase 2: QKV. thread = (lbase = warp*8, co = lane); weights hoisted per-c.
    {
        const int co = t & 31, lbase = (t >> 5) * 8;
        float aq[8], ak[8], av[8];
        const float ibq = bq[co], ibk = bk[co], ibv = bv[co];
        #pragma unroll
        for (int k = 0; k < 8; k++) { aq[k]=ibq; ak[k]=ibk; av[k]=ibv; }
        #pragma unroll 4
        for (int c = 0; c < C_; c++) {
            const float wqv = WQ(co,c), wkv = WK(co,c), wvv = WV(co,c);
            #pragma unroll
            for (int k = 0; k < 8; k++) {
                const float xv = XS(lbase+k, c);     // broadcast within warp
                aq[k] += xv*wqv; ak[k] += xv*wkv; av[k] += xv*wvv;
            }
        }
        #pragma unroll
        for (int k = 0; k < 8; k++) {
            QS(lbase+k,co) = aq[k]; KS(lbase+k,co) = ak[k]; VS(lbase+k,co) = av[k];
        }
    }
    __syncthreads();

    // phase 3: attention, thread = (h,l). Single-pass softmax (scores bounded,
    // max-subtraction unnecessary -> no serial M/Z rescale chain).
    {
        const int h = t >> 6, l = t & 63;
        const int hc = h*D_;
        float qv[D_];
        #pragma unroll
        for (int d = 0; d < D_; d++) qv[d] = QS(l, hc+d);
        const float cw = conv_w[h], cb = conv_b[h];
        const float rsd = 0.35355339059327373f;

        float Z = 0.f, acc[D_];
        #pragma unroll
        for (int d = 0; d < D_; d++) acc[d] = 0.f;

        #pragma unroll 4
        for (int m = 0; m < L_; m++) {
            float sc = 0.f;
            #pragma unroll
            for (int d = 0; d < D_; d++) sc += qv[d]*KS(m, hc+d);   // broadcast
            sc = sc*rsd + BK(l,m)*cw + cb;
            const float p = __expf(sc);
            Z += p;
            #pragma unroll
            for (int d = 0; d < D_; d++) acc[d] += p*VS(m, hc+d);   // broadcast
        }
        const float inv = 1.f/Z;
        float o[D_], og[D_];
        #pragma unroll
        for (int d = 0; d < D_; d++) o[d] = acc[d]*inv;
        #pragma unroll
        for (int d = 0; d < D_; d++) {
            float g = gate_b[hc + d];
            #pragma unroll
            for (int dd = 0; dd < D_; dd++)
                g += gate_w[h*D_*D_ + d*D_ + dd]*o[dd];             // broadcast
            og[d] = o[d] / (1.f + __expf(-g));
        }
        #pragma unroll
        for (int d = 0; d < D_; d++) QS(l, hc+d) = og[d];  // own slots only
    }
    __syncthreads();

    // phase 4a: wo projection + residual -> ks (reuse). All 256 threads.
    {
        const int co = t & 31, lbase = (t >> 5) * 8;
        float acc[8];
        const float ib = bo[co];
        #pragma unroll
        for (int k = 0; k < 8; k++) acc[k] = ib;
        #pragma unroll 4
        for (int c = 0; c < C_; c++) {
            const float w = WO(co,c);
            #pragma unroll
            for (int k = 0; k < 8; k++) acc[k] += QS(lbase+k, c)*w;
        }
        #pragma unroll
        for (int k = 0; k < 8; k++) KS(lbase+k, co) = XS(lbase+k, co) + acc[k];
    }
    __syncthreads();

    // phase 4b: LN(an), quad-parallel, write to g_xbuf (coalesced).
    {
        const int l = t >> 2, q = t & 3;
        float v[8]; float s1 = 0.f, s2 = 0.f;
        #pragma unroll
        for (int j = 0; j < 8; j++) {
            const float val = KS(l, q*8+j);
            v[j] = val; s1 += val; s2 += val*val;
        }
        s1 += __shfl_xor_sync(0xffffffffu, s1, 1); s1 += __shfl_xor_sync(0xffffffffu, s1, 2);
        s2 += __shfl_xor_sync(0xffffffffu, s2, 1); s2 += __shfl_xor_sync(0xffffffffu, s2, 2);
        const float mean = s1*(1.f/C_);
        const float var  = s2*(1.f/C_) - mean*mean;
        const float rstd = rsqrtf(var + 1e-5f);
        float* dst = g_xbuf + ((b*S_ + s)*L_ + l)*C_;
        #pragma unroll
        for (int j = 0; j < 8; j++) {
            const int c = q*8 + j;
            dst[c] = (v[j]-mean)*rstd*an_g[c] + an_b[c];
        }
    }
}

// ---------------------------------------------------------------------------
// Kernel A2: m[b,l,c] = max over tracks s
// ---------------------------------------------------------------------------
__global__ void kMax() {
    const int idx = blockIdx.x*256 + threadIdx.x;
    if (idx < B_*L_*C_) {
        const int b = idx / (L_*C_);
        const int lc = idx - b*(L_*C_);
        float m = g_xbuf[(b*S_)*L_*C_ + lc];
        #pragma unroll
        for (int s = 1; s < S_; s++)
            m = fmaxf(m, g_xbuf[(b*S_ + s)*L_*C_ + lc]);
        g_mbuf[idx] = m;
    }
}

// ---------------------------------------------------------------------------
// Kernel W: wi[b,i,p,d] = sum_c m[b,i,c] * pp_w[p, c*C + d].
// Grid = (b,p) = 512 blocks; pp_w read once per (b,p) slice -> 2MB total
// (vs 128MB when done inside kB).
// ---------------------------------------------------------------------------
__global__ void __launch_bounds__(256) kW(const float* __restrict__ pp_w) {
    __shared__ float ms[L_][C_+1];
    __shared__ float pw[C_][C_+1];
    const int t = threadIdx.x;
    const int b = blockIdx.x >> 4, p = blockIdx.x & 15;

    for (int idx = t; idx < L_*C_; idx += 256)
        ms[idx>>5][idx&31] = g_mbuf[b*L_*C_ + idx];
    for (int idx = t; idx < C_*C_; idx += 256)
        pw[idx>>5][idx&31] = pp_w[p*C_*C_ + idx];
    __syncthreads();

    for (int idx = t; idx < L_*C_; idx += 256) {
        const int i = idx >> 5, d = idx & 31;
        float a = 0.f;
        #pragma unroll 8
        for (int c = 0; c < C_; c++) a += ms[i][c]*pw[c][d];
        g_wibuf[((b*L_ + i)*CP_ + p)*C_ + d] = a;
    }
}

// ---------------------------------------------------------------------------
// Kernel B: block per (b,i). feat[p,j] = wi[p]·m_j / max(|m_i||m_j|,1e-6)+pp_b
// -> AdaNorm over p -> SiLU -> out (B,CP,L,L), contiguous in j.
// ---------------------------------------------------------------------------
__global__ void __launch_bounds__(256) kB(
    const float* __restrict__ pp_b,
    const float* __restrict__ ada_g, const float* __restrict__ ada_b,
    const float* __restrict__ ada_alpha, float* __restrict__ out)
{
    __shared__ float ms[L_][C_+1];
    __shared__ float wiS[CP_][C_+1];
    __shared__ float feat[L_][CP_+1];
    __shared__ float nrm[L_], mu[L_], rs[L_];

    const int t = threadIdx.x;
    const int b = blockIdx.x >> 6, i = blockIdx.x & 63;

    for (int idx = t; idx < L_*C_; idx += 256)
        ms[idx>>5][idx&31] = g_mbuf[b*L_*C_ + idx];
    for (int idx = t; idx < CP_*C_; idx += 256)
        wiS[idx>>5][idx&31] = g_wibuf[(b*L_ + i)*CP_*C_ + idx];
    __syncthreads();

    if (t < L_) {
        float ssum = 0.f;
        #pragma unroll
        for (int c = 0; c < C_; c++) { const float v = ms[t][c]; ssum += v*v; }
        nrm[t] = sqrtf(ssum);
    }
    __syncthreads();

    const float ni = nrm[i];
    for (int idx = t; idx < L_*CP_; idx += 256) {
        const int p = idx >> 6, j = idx & 63;
        float a = 0.f;
        #pragma unroll 8
        for (int d = 0; d < C_; d++) a += wiS[p][d]*ms[j][d];
        feat[j][p] = a / fmaxf(ni*nrm[j], 1e-6f) + pp_b[p];
    }
    __syncthreads();

    if (t < L_) {
        float s1 = 0.f, s2 = 0.f;
        #pragma unroll
        for (int p = 0; p < CP_; p++) { const float v = feat[t][p]; s1 += v; s2 += v*v; }
        const float mean = s1*(1.f/CP_);
        mu[t] = mean; rs[t] = rsqrtf(s2*(1.f/CP_) - mean*mean + 1e-5f);
    }
    __syncthreads();

    const float alpha = ada_alpha[0];
    for (int idx = t; idx < L_*CP_; idx += 256) {
        const int p = idx >> 6, j = idx & 63;
        const float v = feat[j][p];
        const float ln = (v - mu[j])*rs[j]*ada_g[p] + ada_b[p];
        const float val = v + alpha*ln;
        out[((b*CP_ + p)*L_ + i)*L_ + j] = val / (1.f + __expf(-val));
    }
}

extern "C" void kernel_launch(void* const* d_in, const int* in_sizes, int n_in,
                              void* d_out, int out_size) {
    const float* in[29];
    for (int i = 0; i < 29 && i < n_in; i++) in[i] = (const float*)d_in[i];

    cudaFuncSetAttribute(kA, cudaFuncAttributeMaxDynamicSharedMemorySize, KA_SMEM);

    kA<<<B_*S_, 256, KA_SMEM>>>(in[0], in[1], in[2], in[3], in[4],
                                in[5], in[6], in[7], in[8], in[9],
                                in[10], in[11], in[12], in[13], in[14], in[15],
                                in[16], in[17], in[18], in[19],
                                in[20], in[21], in[22], in[23]);
    kMax<<<(B_*L_*C_ + 255)/256, 256>>>();
    kW<<<B_*CP_, 256>>>(in[24]);
    kB<<<B_*L_, 256>>>(in[25], in[26], in[27], in[28], (float*)d_out);
}

// round 3
// speedup vs baseline: 1.3248x; 1.2302x over previous
#include <cuda_runtime.h>

#define B_ 32
#define S_ 4
#define L_ 64
#define C_ 32
#define H_ 4
#define D_ 8
#define CP_ 16

__device__ float g_xbuf[B_*S_*L_*C_];          // post-attn LN'd x
__device__ float g_mbuf[B_*L_*C_];             // max over tracks
__device__ float g_wibuf[B_*L_*CP_*C_];        // wi[b,i,p,d] = m_i^T W_p

// ---------------------------------------------------------------------------
// Kernel A: one block per (b,s), 512 threads.
// smem float layout (rows padded to 36 -> 144B, 16B-aligned float4 rows):
//   XS@0  QS@2304  KS@4608  VS@6912  (64x36 each)
//   WQ@9216 WK@10272 WV@11328 WO@12384 (32x33 each)
//   BK@13440 (64x66)   total 17664 floats = 70656 B
// ---------------------------------------------------------------------------
#define XS(l,c)  sm[(l)*36+(c)]
#define QS(l,c)  sm[2304+(l)*36+(c)]
#define KS(l,c)  sm[4608+(l)*36+(c)]
#define VS(l,c)  sm[6912+(l)*36+(c)]
#define WQ(r,c)  sm[9216+(r)*33+(c)]
#define WK(r,c)  sm[10272+(r)*33+(c)]
#define WV(r,c)  sm[11328+(r)*33+(c)]
#define WO(r,c)  sm[12384+(r)*33+(c)]
#define BK(l,m)  sm[13440+(l)*66+(m)]
#define KA_SMEM  (17664*4)

__global__ void __launch_bounds__(512) kA(
    const float* __restrict__ chip0, const float* __restrict__ chip1,
    const float* __restrict__ chip2, const float* __restrict__ chip3,
    const float* __restrict__ bulk,
    const float* __restrict__ we_w, const float* __restrict__ we_b,
    const float* __restrict__ pos,
    const float* __restrict__ mn_g, const float* __restrict__ mn_b,
    const float* __restrict__ wq, const float* __restrict__ bq,
    const float* __restrict__ wk, const float* __restrict__ bk,
    const float* __restrict__ wv, const float* __restrict__ bv,
    const float* __restrict__ wo, const float* __restrict__ bo,
    const float* __restrict__ an_g, const float* __restrict__ an_b,
    const float* __restrict__ conv_w, const float* __restrict__ conv_b,
    const float* __restrict__ gate_w, const float* __restrict__ gate_b)
{
    extern __shared__ float sm[];
    const int t = threadIdx.x;
    const int bs = blockIdx.x;
    const int b = bs >> 2, s = bs & 3;
    const float* chip = (s==0)?chip0:(s==1)?chip1:(s==2)?chip2:chip3;

    // stage weights + bulk (coalesced)
    for (int idx = t; idx < C_*C_; idx += 512) {
        const int r = idx >> 5, c = idx & 31;
        WQ(r,c) = wq[idx]; WK(r,c) = wk[idx]; WV(r,c) = wv[idx]; WO(r,c) = wo[idx];
    }
    for (int idx = t; idx < L_*L_; idx += 512)
        BK(idx>>6, idx&63) = bulk[b*L_*L_ + idx];

    // phase 1: msa = sig*we_w + we_b + pos; LN(mn). 8 threads per row.
    {
        const int l = t >> 3, oct = t & 7;
        const float sig = chip[b*L_ + l];
        float v[4]; float s1 = 0.f, s2 = 0.f;
        #pragma unroll
        for (int j = 0; j < 4; j++) {
            const int c = oct*4 + j;
            const float val = sig*we_w[c] + we_b[c] + pos[l*C_ + c];
            v[j] = val; s1 += val; s2 += val*val;
        }
        #pragma unroll
        for (int o = 1; o < 8; o <<= 1) {
            s1 += __shfl_xor_sync(0xffffffffu, s1, o);
            s2 += __shfl_xor_sync(0xffffffffu, s2, o);
        }
        const float mean = s1*(1.f/C_);
        const float rstd = rsqrtf(s2*(1.f/C_) - mean*mean + 1e-5f);
        #pragma unroll
        for (int j = 0; j < 4; j++) {
            const int c = oct*4 + j;
            XS(l,c) = (v[j]-mean)*rstd*mn_g[c] + mn_b[c];
        }
    }
    __syncthreads();

    // phase 2: QKV. warp w owns l in [w*4, w*4+4), lane = co.
    {
        const int co = t & 31, lbase = (t >> 5) * 4;
        float aq[4], ak[4], av[4];
        const float ibq = bq[co], ibk = bk[co], ibv = bv[co];
        #pragma unroll
        for (int k = 0; k < 4; k++) { aq[k]=ibq; ak[k]=ibk; av[k]=ibv; }
        #pragma unroll 8
        for (int c = 0; c < C_; c++) {
            const float wqv = WQ(co,c), wkv = WK(co,c), wvv = WV(co,c);
            #pragma unroll
            for (int k = 0; k < 4; k++) {
                const float xv = XS(lbase+k, c);        // warp broadcast
                aq[k] += xv*wqv; ak[k] += xv*wkv; av[k] += xv*wvv;
            }
        }
        #pragma unroll
        for (int k = 0; k < 4; k++) {
            QS(lbase+k,co) = aq[k]; KS(lbase+k,co) = ak[k]; VS(lbase+k,co) = av[k];
        }
    }
    __syncthreads();

    // phase 3: attention. thread = (h, l, half); half splits the m-loop.
    {
        const int h = t >> 7, rem = t & 127;
        const int l = rem >> 1, half = rem & 1;
        const int hc = h*D_;

        float4 q0 = *reinterpret_cast<const float4*>(&QS(l,hc));
        float4 q1 = *reinterpret_cast<const float4*>(&QS(l,hc+4));
        const float cw = conv_w[h], cb = conv_b[h];
        const float rsd = 0.35355339059327373f;  // 1/sqrt(8)

        float Z = 0.f;
        float4 a0 = {0,0,0,0}, a1 = {0,0,0,0};

        #pragma unroll 4
        for (int mm = 0; mm < 32; mm++) {
            const int m = half*32 + mm;
            const float4 k0 = *reinterpret_cast<const float4*>(&KS(m,hc));
            const float4 k1 = *reinterpret_cast<const float4*>(&KS(m,hc+4));
            float sc = q0.x*k0.x + q0.y*k0.y + q0.z*k0.z + q0.w*k0.w
                     + q1.x*k1.x + q1.y*k1.y + q1.z*k1.z + q1.w*k1.w;
            sc = sc*rsd + BK(l,m)*cw + cb;
            const float p = __expf(sc);
            Z += p;
            const float4 v0 = *reinterpret_cast<const float4*>(&VS(m,hc));
            const float4 v1 = *reinterpret_cast<const float4*>(&VS(m,hc+4));
            a0.x += p*v0.x; a0.y += p*v0.y; a0.z += p*v0.z; a0.w += p*v0.w;
            a1.x += p*v1.x; a1.y += p*v1.y; a1.z += p*v1.z; a1.w += p*v1.w;
        }
        // combine halves (partner = lane^1)
        Z   += __shfl_xor_sync(0xffffffffu, Z, 1);
        a0.x += __shfl_xor_sync(0xffffffffu, a0.x, 1);
        a0.y += __shfl_xor_sync(0xffffffffu, a0.y, 1);
        a0.z += __shfl_xor_sync(0xffffffffu, a0.z, 1);
        a0.w += __shfl_xor_sync(0xffffffffu, a0.w, 1);
        a1.x += __shfl_xor_sync(0xffffffffu, a1.x, 1);
        a1.y += __shfl_xor_sync(0xffffffffu, a1.y, 1);
        a1.z += __shfl_xor_sync(0xffffffffu, a1.z, 1);
        a1.w += __shfl_xor_sync(0xffffffffu, a1.w, 1);

        __syncthreads();              // all QS reads complete before overwrite
        if (half == 0) {
            const float inv = 1.f/Z;
            float o[D_];
            o[0]=a0.x*inv; o[1]=a0.y*inv; o[2]=a0.z*inv; o[3]=a0.w*inv;
            o[4]=a1.x*inv; o[5]=a1.y*inv; o[6]=a1.z*inv; o[7]=a1.w*inv;
            #pragma unroll
            for (int d = 0; d < D_; d++) {
                float g = gate_b[hc + d];
                #pragma unroll
                for (int dd = 0; dd < D_; dd++)
                    g += gate_w[h*D_*D_ + d*D_ + dd]*o[dd];
                QS(l, hc+d) = o[d] / (1.f + __expf(-g));
            }
        }
    }
    __syncthreads();

    // phase 4a: wo projection + residual -> KS (reuse).
    {
        const int co = t & 31, lbase = (t >> 5) * 4;
        float acc[4];
        const float ib = bo[co];
        #pragma unroll
        for (int k = 0; k < 4; k++) acc[k] = ib;
        #pragma unroll 8
        for (int c = 0; c < C_; c++) {
            const float w = WO(co,c);
            #pragma unroll
            for (int k = 0; k < 4; k++) acc[k] += QS(lbase+k, c)*w;
        }
        #pragma unroll
        for (int k = 0; k < 4; k++) KS(lbase+k, co) = XS(lbase+k, co) + acc[k];
    }
    __syncthreads();

    // phase 4b: LN(an) -> g_xbuf. 8 threads per row.
    {
        const int l = t >> 3, oct = t & 7;
        float v[4]; float s1 = 0.f, s2 = 0.f;
        #pragma unroll
        for (int j = 0; j < 4; j++) {
            const float val = KS(l, oct*4+j);
            v[j] = val; s1 += val; s2 += val*val;
        }
        #pragma unroll
        for (int o = 1; o < 8; o <<= 1) {
            s1 += __shfl_xor_sync(0xffffffffu, s1, o);
            s2 += __shfl_xor_sync(0xffffffffu, s2, o);
        }
        const float mean = s1*(1.f/C_);
        const float rstd = rsqrtf(s2*(1.f/C_) - mean*mean + 1e-5f);
        float* dst = g_xbuf + ((b*S_ + s)*L_ + l)*C_;
        #pragma unroll
        for (int j = 0; j < 4; j++) {
            const int c = oct*4 + j;
            dst[c] = (v[j]-mean)*rstd*an_g[c] + an_b[c];
        }
    }
}

// ---------------------------------------------------------------------------
// Kernel A2: m[b,l,c] = max over tracks s
// ---------------------------------------------------------------------------
__global__ void kMax() {
    const int idx = blockIdx.x*256 + threadIdx.x;
    if (idx < B_*L_*C_) {
        const int b = idx / (L_*C_);
        const int lc = idx - b*(L_*C_);
        float m = g_xbuf[(b*S_)*L_*C_ + lc];
        #pragma unroll
        for (int s = 1; s < S_; s++)
            m = fmaxf(m, g_xbuf[(b*S_ + s)*L_*C_ + lc]);
        g_mbuf[idx] = m;
    }
}

// ---------------------------------------------------------------------------
// Kernel W: wi[b,i,p,d] = sum_c m[b,i,c] * pp_w[p, c*C + d].  grid=(b,p)=512.
// ---------------------------------------------------------------------------
__global__ void __launch_bounds__(256) kW(const float* __restrict__ pp_w) {
    __shared__ float ms[L_][C_+1];
    __shared__ float pw[C_][C_+1];
    const int t = threadIdx.x;
    const int b = blockIdx.x >> 4, p = blockIdx.x & 15;

    for (int idx = t; idx < L_*C_; idx += 256)
        ms[idx>>5][idx&31] = g_mbuf[b*L_*C_ + idx];
    for (int idx = t; idx < C_*C_; idx += 256)
        pw[idx>>5][idx&31] = pp_w[p*C_*C_ + idx];
    __syncthreads();

    const int d = t & 31, ig = t >> 5;      // 8 i's per thread
    float acc[8];
    #pragma unroll
    for (int k = 0; k < 8; k++) acc[k] = 0.f;
    #pragma unroll 8
    for (int c = 0; c < C_; c++) {
        const float w = pw[c][d];
        #pragma unroll
        for (int k = 0; k < 8; k++) acc[k] += ms[ig*8+k][c]*w;
    }
    #pragma unroll
    for (int k = 0; k < 8; k++)
        g_wibuf[((b*L_ + ig*8+k)*CP_ + p)*C_ + d] = acc[k];
}

// ---------------------------------------------------------------------------
// Kernel B: block per (b, 4-i-group). Register-tiled 4j x 4p per thread with
// float4 LDS.  feat -> AdaNorm -> SiLU -> out (B,CP,L,L).
// ---------------------------------------------------------------------------
__global__ void __launch_bounds__(256) kB(
    const float* __restrict__ pp_b,
    const float* __restrict__ ada_g, const float* __restrict__ ada_b,
    const float* __restrict__ ada_alpha, float* __restrict__ out)
{
    __shared__ float msB[L_][36];            // 144B rows, float4-aligned
    __shared__ float wiB[4][CP_][36];
    __shared__ float feat[4][L_][CP_+1];
    __shared__ float nrm[L_];

    const int t = threadIdx.x;
    const int b = blockIdx.x >> 4, i0 = (blockIdx.x & 15) * 4;

    for (int idx = t; idx < L_*C_; idx += 256)
        msB[idx>>5][idx&31] = g_mbuf[b*L_*C_ + idx];
    {
        const float* src = g_wibuf + (b*L_ + i0)*CP_*C_;
        for (int idx = t; idx < 4*CP_*C_; idx += 256)
            wiB[idx>>9][(idx>>5)&15][idx&31] = src[idx];
    }
    __syncthreads();

    if (t < L_) {
        float ssum = 0.f;
        #pragma unroll
        for (int c = 0; c < C_; c++) { const float v = msB[t][c]; ssum += v*v; }
        nrm[t] = sqrtf(ssum);
    }
    __syncthreads();

    // main GEMM-let: thread -> (ii, p-group of 4, j-group of 4)
    {
        const int ii = t >> 6, sub = t & 63;
        const int p0 = (sub >> 4) * 4, j0 = (sub & 15) * 4;
        float acc[4][4];
        #pragma unroll
        for (int pk = 0; pk < 4; pk++)
            #pragma unroll
            for (int jk = 0; jk < 4; jk++) acc[pk][jk] = 0.f;

        #pragma unroll
        for (int ch = 0; ch < 8; ch++) {
            const int cd = ch*4;
            float4 mj[4], wp[4];
            #pragma unroll
            for (int jk = 0; jk < 4; jk++)
                mj[jk] = *reinterpret_cast<const float4*>(&msB[j0+jk][cd]);
            #pragma unroll
            for (int pk = 0; pk < 4; pk++)
                wp[pk] = *reinterpret_cast<const float4*>(&wiB[ii][p0+pk][cd]);
            #pragma unroll
            for (int pk = 0; pk < 4; pk++)
                #pragma unroll
                for (int jk = 0; jk < 4; jk++)
                    acc[pk][jk] += wp[pk].x*mj[jk].x + wp[pk].y*mj[jk].y
                                 + wp[pk].z*mj[jk].z + wp[pk].w*mj[jk].w;
        }
        const float ni = nrm[i0+ii];
        #pragma unroll
        for (int pk = 0; pk < 4; pk++) {
            const float bp = pp_b[p0+pk];
            #pragma unroll
            for (int jk = 0; jk < 4; jk++) {
                const int j = j0+jk;
                feat[ii][j][p0+pk] =
                    __fdividef(acc[pk][jk], fmaxf(ni*nrm[j], 1e-6f)) + bp;
            }
        }
    }
    __syncthreads();

    __shared__ float mu[4][L_], rs[4][L_];
    {
        const int ii = t >> 6, j = t & 63;
        float s1 = 0.f, s2 = 0.f;
        #pragma unroll
        for (int p = 0; p < CP_; p++) {
            const float v = feat[ii][j][p]; s1 += v; s2 += v*v;
        }
        const float mean = s1*(1.f/CP_);
        mu[ii][j] = mean;
        rs[ii][j] = rsqrtf(s2*(1.f/CP_) - mean*mean + 1e-5f);
    }
    __syncthreads();

    const float alpha = ada_alpha[0];
    for (int idx = t; idx < 4*CP_*L_; idx += 256) {
        const int ii = idx >> 10, p = (idx >> 6) & 15, j = idx & 63;
        const float v = feat[ii][j][p];
        const float ln = (v - mu[ii][j])*rs[ii][j]*ada_g[p] + ada_b[p];
        const float val = v + alpha*ln;
        out[((b*CP_ + p)*L_ + i0+ii)*L_ + j] = val / (1.f + __expf(-val));
    }
}

extern "C" void kernel_launch(void* const* d_in, const int* in_sizes, int n_in,
                              void* d_out, int out_size) {
    const float* in[29];
    for (int i = 0; i < 29 && i < n_in; i++) in[i] = (const float*)d_in[i];

    cudaFuncSetAttribute(kA, cudaFuncAttributeMaxDynamicSharedMemorySize, KA_SMEM);

    kA<<<B_*S_, 512, KA_SMEM>>>(in[0], in[1], in[2], in[3], in[4],
                                in[5], in[6], in[7], in[8], in[9],
                                in[10], in[11], in[12], in[13], in[14], in[15],
                                in[16], in[17], in[18], in[19],
                                in[20], in[21], in[22], in[23]);
    kMax<<<(B_*L_*C_ + 255)/256, 256>>>();
    kW<<<B_*CP_, 256>>>(in[24]);
    kB<<<B_*L_/4, 256>>>(in[25], in[26], in[27], in[28], (float*)d_out);
}

// round 4
// speedup vs baseline: 1.4095x; 1.0640x over previous
#include <cuda_runtime.h>

#define B_ 32
#define S_ 4
#define L_ 64
#define C_ 32
#define H_ 4
#define D_ 8
#define CP_ 16

typedef unsigned long long u64;

__device__ __forceinline__ u64 fma2(u64 a, u64 b, u64 c){
    u64 d; asm("fma.rn.f32x2 %0,%1,%2,%3;" : "=l"(d) : "l"(a),"l"(b),"l"(c)); return d;
}
__device__ __forceinline__ u64 mul2(u64 a, u64 b){
    u64 d; asm("mul.rn.f32x2 %0,%1,%2;" : "=l"(d) : "l"(a),"l"(b)); return d;
}
__device__ __forceinline__ u64 add2(u64 a, u64 b){
    u64 d; asm("add.rn.f32x2 %0,%1,%2;" : "=l"(d) : "l"(a),"l"(b)); return d;
}
__device__ __forceinline__ u64 pack2(float lo, float hi){
    u64 d; asm("mov.b64 %0,{%1,%2};" : "=l"(d) : "f"(lo),"f"(hi)); return d;
}
__device__ __forceinline__ float2 unpack2(u64 v){
    float x,y; asm("mov.b64 {%0,%1},%2;" : "=f"(x),"=f"(y) : "l"(v)); return make_float2(x,y);
}

__device__ float g_xbuf[B_*S_*L_*C_];
__device__ float g_mbuf[B_*L_*C_];
__device__ float g_nrm[B_*L_];
__device__ float g_wibuf[B_*L_*CP_*C_];

// row swizzles: keep float4 alignment (key is a multiple of 4 < 32)
__device__ __forceinline__ int xi(int r, int c){           // kA tiles (rows 0..63)
    const int key = (((r>>2)&7) ^ (((r>>5)&1)<<2)) << 2;   // m vs m+32 -> different banks
    return r*36 + (c ^ key);
}
__device__ __forceinline__ int swz(int r, int c){          // kB tiles
    return r*36 + (c ^ (((r>>2)&7)<<2));
}

// ---------------------------------------------------------------------------
// Kernel A: one block per (b,s), 512 threads. Dynamic smem:
//  XS@0 QS@2304 KS@4608 VS@6912 (64x36 swizzled)
//  WQ@9216 WK@10272 WV@11328 WO@12384 (32x33)
//  BK@13440: two half-planes [half][64][66], plane stride 4225 (+1 de-conflict)
//  total 21890 floats = 87560 B
// ---------------------------------------------------------------------------
#define KA_SMEM (21890*4)
#define BKI(l,m) (13440 + ((m)>>5)*4225 + (l)*66 + ((m)&31))

__global__ void __launch_bounds__(512) kA(
    const float* __restrict__ chip0, const float* __restrict__ chip1,
    const float* __restrict__ chip2, const float* __restrict__ chip3,
    const float* __restrict__ bulk,
    const float* __restrict__ we_w, const float* __restrict__ we_b,
    const float* __restrict__ pos,
    const float* __restrict__ mn_g, const float* __restrict__ mn_b,
    const float* __restrict__ wq, const float* __restrict__ bq,
    const float* __restrict__ wk, const float* __restrict__ bk,
    const float* __restrict__ wv, const float* __restrict__ bv,
    const float* __restrict__ wo, const float* __restrict__ bo,
    const float* __restrict__ an_g, const float* __restrict__ an_b,
    const float* __restrict__ conv_w, const float* __restrict__ conv_b,
    const float* __restrict__ gate_w, const float* __restrict__ gate_b)
{
    extern __shared__ float sm[];
    const int t = threadIdx.x;
    const int b = blockIdx.x >> 2, s = blockIdx.x & 3;
    const float* chip = (s==0)?chip0:(s==1)?chip1:(s==2)?chip2:chip3;

    for (int idx = t; idx < C_*C_; idx += 512) {
        const int r = idx >> 5, c = idx & 31;
        sm[9216 + r*33 + c]  = wq[idx];
        sm[10272 + r*33 + c] = wk[idx];
        sm[11328 + r*33 + c] = wv[idx];
        sm[12384 + r*33 + c] = wo[idx];
    }
    for (int idx = t; idx < L_*L_; idx += 512)
        sm[BKI(idx>>6, idx&63)] = bulk[b*L_*L_ + idx];

    // phase 1: msa + pos, LN(mn). 8 threads per row.
    {
        const int l = t >> 3, oct = t & 7;
        const float sig = chip[b*L_ + l];
        float v[4]; float s1 = 0.f, s2 = 0.f;
        #pragma unroll
        for (int j = 0; j < 4; j++) {
            const int c = oct*4 + j;
            const float val = sig*we_w[c] + we_b[c] + pos[l*C_ + c];
            v[j] = val; s1 += val; s2 += val*val;
        }
        #pragma unroll
        for (int o = 1; o < 8; o <<= 1) {
            s1 += __shfl_xor_sync(0xffffffffu, s1, o);
            s2 += __shfl_xor_sync(0xffffffffu, s2, o);
        }
        const float mean = s1*(1.f/C_);
        const float rstd = rsqrtf(s2*(1.f/C_) - mean*mean + 1e-5f);
        #pragma unroll
        for (int j = 0; j < 4; j++) {
            const int c = oct*4 + j;
            sm[xi(l,c)] = (v[j]-mean)*rstd*mn_g[c] + mn_b[c];
        }
    }
    __syncthreads();

    // phase 2: QKV. warp w -> rows [4w,4w+4), lane = co.
    {
        const int co = t & 31, lbase = (t >> 5) * 4;
        float aq[4], ak[4], av[4];
        const float ibq = bq[co], ibk = bk[co], ibv = bv[co];
        #pragma unroll
        for (int k = 0; k < 4; k++) { aq[k]=ibq; ak[k]=ibk; av[k]=ibv; }
        #pragma unroll 8
        for (int c = 0; c < C_; c++) {
            const float wqv = sm[9216 + co*33 + c];
            const float wkv = sm[10272 + co*33 + c];
            const float wvv = sm[11328 + co*33 + c];
            #pragma unroll
            for (int k = 0; k < 4; k++) {
                const float xv = sm[xi(lbase+k, c)];    // broadcast
                aq[k] += xv*wqv; ak[k] += xv*wkv; av[k] += xv*wvv;
            }
        }
        #pragma unroll
        for (int k = 0; k < 4; k++) {
            sm[2304 + xi(lbase+k,co)] = aq[k];
            sm[4608 + xi(lbase+k,co)] = ak[k];
            sm[6912 + xi(lbase+k,co)] = av[k];
        }
    }
    __syncthreads();

    // phase 3: attention, thread = (h,l,half). f32x2 packed math.
    {
        const int h = t >> 7, rem = t & 127;
        const int l = rem >> 1, half = rem & 1;
        const int hc = h*D_;
        const float rsd = 0.35355339059327373f;

        ulonglong2 qa = *reinterpret_cast<const ulonglong2*>(&sm[2304 + xi(l,hc)]);
        ulonglong2 qb = *reinterpret_cast<const ulonglong2*>(&sm[2304 + xi(l,hc+4)]);
        const u64 rsd2 = pack2(rsd, rsd);
        qa.x = mul2(qa.x, rsd2); qa.y = mul2(qa.y, rsd2);
        qb.x = mul2(qb.x, rsd2); qb.y = mul2(qb.y, rsd2);
        const float cw = conv_w[h], cb = conv_b[h];

        float Z = 0.f;
        u64 A0 = 0ull, A1 = 0ull, A2 = 0ull, A3 = 0ull;

        #pragma unroll 4
        for (int mm = 0; mm < 32; mm++) {
            const int m = half*32 + mm;
            const ulonglong2 ka = *reinterpret_cast<const ulonglong2*>(&sm[4608 + xi(m,hc)]);
            const ulonglong2 kb = *reinterpret_cast<const ulonglong2*>(&sm[4608 + xi(m,hc+4)]);
            u64 u = mul2(qa.x, ka.x);
            u = fma2(qa.y, ka.y, u);
            u = fma2(qb.x, kb.x, u);
            u = fma2(qb.y, kb.y, u);
            const float2 uf = unpack2(u);
            const float sc = uf.x + uf.y + fmaf(sm[BKI(l,m)], cw, cb);
            const float p = __expf(sc);
            Z += p;
            const u64 pp = pack2(p, p);
            const ulonglong2 va = *reinterpret_cast<const ulonglong2*>(&sm[6912 + xi(m,hc)]);
            const ulonglong2 vb = *reinterpret_cast<const ulonglong2*>(&sm[6912 + xi(m,hc+4)]);
            A0 = fma2(pp, va.x, A0); A1 = fma2(pp, va.y, A1);
            A2 = fma2(pp, vb.x, A2); A3 = fma2(pp, vb.y, A3);
        }
        Z  += __shfl_xor_sync(0xffffffffu, Z, 1);
        A0 = add2(A0, __shfl_xor_sync(0xffffffffu, A0, 1));
        A1 = add2(A1, __shfl_xor_sync(0xffffffffu, A1, 1));
        A2 = add2(A2, __shfl_xor_sync(0xffffffffu, A2, 1));
        A3 = add2(A3, __shfl_xor_sync(0xffffffffu, A3, 1));

        __syncthreads();
        if (half == 0) {
            const float inv = 1.f/Z;
            const float2 f0 = unpack2(A0), f1 = unpack2(A1), f2 = unpack2(A2), f3 = unpack2(A3);
            float o[D_];
            o[0]=f0.x*inv; o[1]=f0.y*inv; o[2]=f1.x*inv; o[3]=f1.y*inv;
            o[4]=f2.x*inv; o[5]=f2.y*inv; o[6]=f3.x*inv; o[7]=f3.y*inv;
            #pragma unroll
            for (int d = 0; d < D_; d++) {
                float g = gate_b[hc + d];
                #pragma unroll
                for (int dd = 0; dd < D_; dd++)
                    g += gate_w[h*D_*D_ + d*D_ + dd]*o[dd];
                sm[2304 + xi(l, hc+d)] = o[d] / (1.f + __expf(-g));
            }
        }
    }
    __syncthreads();

    // phase 4a: wo + residual -> KS
    {
        const int co = t & 31, lbase = (t >> 5) * 4;
        float acc[4];
        const float ib = bo[co];
        #pragma unroll
        for (int k = 0; k < 4; k++) acc[k] = ib;
        #pragma unroll 8
        for (int c = 0; c < C_; c++) {
            const float w = sm[12384 + co*33 + c];
            #pragma unroll
            for (int k = 0; k < 4; k++) acc[k] += sm[2304 + xi(lbase+k, c)]*w;
        }
        #pragma unroll
        for (int k = 0; k < 4; k++)
            sm[4608 + xi(lbase+k, co)] = sm[xi(lbase+k, co)] + acc[k];
    }
    __syncthreads();

    // phase 4b: LN(an) -> g_xbuf
    {
        const int l = t >> 3, oct = t & 7;
        float v[4]; float s1 = 0.f, s2 = 0.f;
        #pragma unroll
        for (int j = 0; j < 4; j++) {
            const float val = sm[4608 + xi(l, oct*4+j)];
            v[j] = val; s1 += val; s2 += val*val;
        }
        #pragma unroll
        for (int o = 1; o < 8; o <<= 1) {
            s1 += __shfl_xor_sync(0xffffffffu, s1, o);
            s2 += __shfl_xor_sync(0xffffffffu, s2, o);
        }
        const float mean = s1*(1.f/C_);
        const float rstd = rsqrtf(s2*(1.f/C_) - mean*mean + 1e-5f);
        float* dst = g_xbuf + ((b*S_ + s)*L_ + l)*C_;
        #pragma unroll
        for (int j = 0; j < 4; j++) {
            const int c = oct*4 + j;
            dst[c] = (v[j]-mean)*rstd*an_g[c] + an_b[c];
        }
    }
}

// ---------------------------------------------------------------------------
// Kernel W: fused max-over-tracks + wi projection + (p==0) m/nrm emission.
// grid = (b,p) = 512 blocks, 256 threads.
// ---------------------------------------------------------------------------
__global__ void __launch_bounds__(256) kW(const float* __restrict__ pp_w) {
    __shared__ float ms[L_][C_+1];
    __shared__ float pw[C_][C_+1];
    const int t = threadIdx.x;
    const int b = blockIdx.x >> 4, p = blockIdx.x & 15;
    const float* xb = g_xbuf + b*S_*L_*C_;

    for (int idx = t; idx < L_*C_; idx += 256) {
        float m = fmaxf(fmaxf(xb[idx], xb[2048+idx]),
                        fmaxf(xb[4096+idx], xb[6144+idx]));
        ms[idx>>5][idx&31] = m;
        if (p == 0) g_mbuf[b*L_*C_ + idx] = m;
    }
    for (int idx = t; idx < C_*C_; idx += 256)
        pw[idx>>5][idx&31] = pp_w[p*C_*C_ + idx];
    __syncthreads();

    if (p == 0 && t < L_) {
        float ssum = 0.f;
        #pragma unroll
        for (int c = 0; c < C_; c++) { const float v = ms[t][c]; ssum += v*v; }
        g_nrm[b*L_ + t] = sqrtf(ssum);
    }

    const int d = t & 31, ig = t >> 5;     // 8 i's per thread
    float acc[8];
    #pragma unroll
    for (int k = 0; k < 8; k++) acc[k] = 0.f;
    #pragma unroll 8
    for (int c = 0; c < C_; c++) {
        const float w = pw[c][d];
        #pragma unroll
        for (int k = 0; k < 8; k++) acc[k] += ms[ig*8+k][c]*w;
    }
    #pragma unroll
    for (int k = 0; k < 8; k++)
        g_wibuf[((b*L_ + ig*8+k)*CP_ + p)*C_ + d] = acc[k];
}

// ---------------------------------------------------------------------------
// Kernel B: grid = (b, i-pair) = 1024 blocks, 256 threads.
// Thread tile: 2 p (pq, pq+8) x 4 j. feat entirely in registers; AdaNorm via
// shfl over the 8 threads (pq=0..7) sharing (ii,jg). Direct float4 stores.
// ---------------------------------------------------------------------------
__global__ void __launch_bounds__(256) kB(
    const float* __restrict__ pp_b,
    const float* __restrict__ ada_g, const float* __restrict__ ada_b,
    const float* __restrict__ ada_alpha, float* __restrict__ out)
{
    __shared__ float msB[64*36];
    __shared__ float wiB[2*16*36];
    __shared__ float nrmS[L_];

    const int t = threadIdx.x;
    const int b = blockIdx.x >> 5, i0 = (blockIdx.x & 31) * 2;

    for (int idx = t; idx < L_*C_; idx += 256)
        msB[swz(idx>>5, idx&31)] = g_mbuf[b*L_*C_ + idx];
    for (int idx = t; idx < 2*CP_*C_; idx += 256) {
        const int ii = idx >> 9, p = (idx >> 5) & 15, d = idx & 31;
        wiB[ii*576 + swz(p,d)] = g_wibuf[(b*L_ + i0)*CP_*C_ + idx];
    }
    if (t < L_) nrmS[t] = g_nrm[b*L_ + t];
    __syncthreads();

    const int ii = t >> 7, sub = t & 127;
    const int jg = sub >> 3, j0 = jg*4;
    const int pq = sub & 7;
    const int i = i0 + ii;

    u64 acc[2][4];
    #pragma unroll
    for (int pk = 0; pk < 2; pk++)
        #pragma unroll
        for (int jk = 0; jk < 4; jk++) acc[pk][jk] = 0ull;

    #pragma unroll
    for (int ch = 0; ch < 8; ch++) {
        const int cd = ch*4;
        ulonglong2 mj[4], wp[2];
        #pragma unroll
        for (int jk = 0; jk < 4; jk++)
            mj[jk] = *reinterpret_cast<const ulonglong2*>(&msB[swz(j0+jk, cd)]);
        #pragma unroll
        for (int pk = 0; pk < 2; pk++)
            wp[pk] = *reinterpret_cast<const ulonglong2*>(&wiB[ii*576 + swz(pq+8*pk, cd)]);
        #pragma unroll
        for (int pk = 0; pk < 2; pk++)
            #pragma unroll
            for (int jk = 0; jk < 4; jk++) {
                acc[pk][jk] = fma2(wp[pk].x, mj[jk].x, acc[pk][jk]);
                acc[pk][jk] = fma2(wp[pk].y, mj[jk].y, acc[pk][jk]);
            }
    }

    const float ni = nrmS[i];
    float invd[4];
    #pragma unroll
    for (int jk = 0; jk < 4; jk++)
        invd[jk] = __fdividef(1.f, fmaxf(ni*nrmS[j0+jk], 1e-6f));

    float feat[2][4];
    #pragma unroll
    for (int pk = 0; pk < 2; pk++) {
        const float bp = pp_b[pq + 8*pk];
        #pragma unroll
        for (int jk = 0; jk < 4; jk++) {
            const float2 f = unpack2(acc[pk][jk]);
            feat[pk][jk] = (f.x + f.y)*invd[jk] + bp;
        }
    }

    // AdaNorm stats over all 16 p: 2 local + shfl over 8 threads (pq)
    float s1[4], s2[4];
    #pragma unroll
    for (int jk = 0; jk < 4; jk++) {
        s1[jk] = feat[0][jk] + feat[1][jk];
        s2[jk] = feat[0][jk]*feat[0][jk] + feat[1][jk]*feat[1][jk];
    }
    #pragma unroll
    for (int o = 1; o < 8; o <<= 1) {
        #pragma unroll
        for (int jk = 0; jk < 4; jk++) {
            s1[jk] += __shfl_xor_sync(0xffffffffu, s1[jk], o);
            s2[jk] += __shfl_xor_sync(0xffffffffu, s2[jk], o);
        }
    }
    float mu[4], rsd[4];
    #pragma unroll
    for (int jk = 0; jk < 4; jk++) {
        mu[jk] = s1[jk]*(1.f/CP_);
        rsd[jk] = rsqrtf(s2[jk]*(1.f/CP_) - mu[jk]*mu[jk] + 1e-5f);
    }

    const float alpha = ada_alpha[0];
    #pragma unroll
    for (int pk = 0; pk < 2; pk++) {
        const int p = pq + 8*pk;
        const float g = ada_g[p], bb = ada_b[p];
        float4 r;
        float* rp = &r.x;
        #pragma unroll
        for (int jk = 0; jk < 4; jk++) {
            const float v = feat[pk][jk];
            const float ln = (v - mu[jk])*rsd[jk]*g + bb;
            const float val = v + alpha*ln;
            rp[jk] = __fdividef(val, 1.f + __expf(-val));
        }
        *reinterpret_cast<float4*>(&out[((b*CP_ + p)*L_ + i)*L_ + j0]) = r;
    }
}

extern "C" void kernel_launch(void* const* d_in, const int* in_sizes, int n_in,
                              void* d_out, int out_size) {
    const float* in[29];
    for (int i = 0; i < 29 && i < n_in; i++) in[i] = (const float*)d_in[i];

    cudaFuncSetAttribute(kA, cudaFuncAttributeMaxDynamicSharedMemorySize, KA_SMEM);

    kA<<<B_*S_, 512, KA_SMEM>>>(in[0], in[1], in[2], in[3], in[4],
                                in[5], in[6], in[7], in[8], in[9],
                                in[10], in[11], in[12], in[13], in[14], in[15],
                                in[16], in[17], in[18], in[19],
                                in[20], in[21], in[22], in[23]);
    kW<<<B_*CP_, 256>>>(in[24]);
    kB<<<B_*L_/2, 256>>>(in[25], in[26], in[27], in[28], (float*)d_out);
}

// round 5
// speedup vs baseline: 1.4573x; 1.0339x over previous
#include <cuda_runtime.h>

#define B_ 32
#define S_ 4
#define L_ 64
#define C_ 32
#define H_ 4
#define D_ 8
#define CP_ 16

typedef unsigned long long u64;

__device__ __forceinline__ u64 fma2(u64 a, u64 b, u64 c){
    u64 d; asm("fma.rn.f32x2 %0,%1,%2,%3;" : "=l"(d) : "l"(a),"l"(b),"l"(c)); return d;
}
__device__ __forceinline__ u64 mul2(u64 a, u64 b){
    u64 d; asm("mul.rn.f32x2 %0,%1,%2;" : "=l"(d) : "l"(a),"l"(b)); return d;
}
__device__ __forceinline__ u64 add2(u64 a, u64 b){
    u64 d; asm("add.rn.f32x2 %0,%1,%2;" : "=l"(d) : "l"(a),"l"(b)); return d;
}
__device__ __forceinline__ u64 pack2(float lo, float hi){
    u64 d; asm("mov.b64 %0,{%1,%2};" : "=l"(d) : "f"(lo),"f"(hi)); return d;
}
__device__ __forceinline__ float2 unpack2(u64 v){
    float x,y; asm("mov.b64 {%0,%1},%2;" : "=f"(x),"=f"(y) : "l"(v)); return make_float2(x,y);
}

__device__ float g_xbuf[B_*S_*L_*C_];
__device__ float g_mbuf[B_*L_*C_];
__device__ float g_nrm[B_*L_];
__device__ float g_wibuf[B_*L_*CP_*C_];

// row swizzles (key multiple of 4 -> float4 alignment preserved)
__device__ __forceinline__ int xi(int r, int c){
    const int key = (((r>>2)&7) ^ (((r>>5)&1)<<2)) << 2;
    return r*36 + (c ^ key);
}
__device__ __forceinline__ int swz(int r, int c){
    return r*36 + (c ^ (((r>>2)&7)<<2));
}

// ---------------------------------------------------------------------------
// Kernel A: one block per (b,s), 1024 threads.
// smem floats: XS@0 QS@2304 KS@4608 VS@6912 (64x36 swizzled)
//   WQ@9216 WK@10272 WV@11328 WO@12384 (32x33)
//   BK@13440 (two planes, stride 4225)
//   GW@21890 (256) GB@22146 (32)   total 22178 floats
// ---------------------------------------------------------------------------
#define KA_SMEM (22178*4)
#define BKI(l,m) (13440 + ((m)>>5)*4225 + (l)*66 + ((m)&31))

__global__ void __launch_bounds__(1024) kA(
    const float* __restrict__ chip0, const float* __restrict__ chip1,
    const float* __restrict__ chip2, const float* __restrict__ chip3,
    const float* __restrict__ bulk,
    const float* __restrict__ we_w, const float* __restrict__ we_b,
    const float* __restrict__ pos,
    const float* __restrict__ mn_g, const float* __restrict__ mn_b,
    const float* __restrict__ wq, const float* __restrict__ bq,
    const float* __restrict__ wk, const float* __restrict__ bk,
    const float* __restrict__ wv, const float* __restrict__ bv,
    const float* __restrict__ wo, const float* __restrict__ bo,
    const float* __restrict__ an_g, const float* __restrict__ an_b,
    const float* __restrict__ conv_w, const float* __restrict__ conv_b,
    const float* __restrict__ gate_w, const float* __restrict__ gate_b)
{
    extern __shared__ float sm[];
    const int t = threadIdx.x;
    const int b = blockIdx.x >> 2, s = blockIdx.x & 3;
    const float* chip = (s==0)?chip0:(s==1)?chip1:(s==2)?chip2:chip3;

    for (int idx = t; idx < C_*C_; idx += 1024) {
        const int r = idx >> 5, c = idx & 31;
        sm[9216 + r*33 + c]  = wq[idx];
        sm[10272 + r*33 + c] = wk[idx];
        sm[11328 + r*33 + c] = wv[idx];
        sm[12384 + r*33 + c] = wo[idx];
    }
    for (int idx = t; idx < L_*L_; idx += 1024)
        sm[BKI(idx>>6, idx&63)] = bulk[b*L_*L_ + idx];
    if (t < 256) sm[21890 + t] = gate_w[t];
    if (t >= 256 && t < 288) sm[22146 + t - 256] = gate_b[t - 256];

    // phase 1: msa + pos, LN(mn). 16 threads/row, 2 c each.
    {
        const int l = t >> 4, q = t & 15, c0 = q*2;
        const float sig = chip[b*L_ + l];
        const float2 ww = *reinterpret_cast<const float2*>(&we_w[c0]);
        const float2 wb = *reinterpret_cast<const float2*>(&we_b[c0]);
        const float2 pp = *reinterpret_cast<const float2*>(&pos[l*C_ + c0]);
        float v0 = fmaf(sig, ww.x, wb.x) + pp.x;
        float v1 = fmaf(sig, ww.y, wb.y) + pp.y;
        float s1 = v0 + v1, s2 = v0*v0 + v1*v1;
        #pragma unroll
        for (int o = 1; o < 16; o <<= 1) {
            s1 += __shfl_xor_sync(0xffffffffu, s1, o);
            s2 += __shfl_xor_sync(0xffffffffu, s2, o);
        }
        const float mean = s1*(1.f/C_);
        const float rstd = rsqrtf(s2*(1.f/C_) - mean*mean + 1e-5f);
        sm[xi(l,c0)]   = (v0-mean)*rstd*mn_g[c0]   + mn_b[c0];
        sm[xi(l,c0+1)] = (v1-mean)*rstd*mn_g[c0+1] + mn_b[c0+1];
    }
    __syncthreads();

    // phase 2: QKV. warp -> 2 rows, lane = co.
    {
        const int co = t & 31, lbase = (t >> 5) * 2;
        float aq[2], ak[2], av[2];
        const float ibq = bq[co], ibk = bk[co], ibv = bv[co];
        #pragma unroll
        for (int k = 0; k < 2; k++) { aq[k]=ibq; ak[k]=ibk; av[k]=ibv; }
        #pragma unroll 8
        for (int c = 0; c < C_; c++) {
            const float wqv = sm[9216 + co*33 + c];
            const float wkv = sm[10272 + co*33 + c];
            const float wvv = sm[11328 + co*33 + c];
            #pragma unroll
            for (int k = 0; k < 2; k++) {
                const float xv = sm[xi(lbase+k, c)];
                aq[k] += xv*wqv; ak[k] += xv*wkv; av[k] += xv*wvv;
            }
        }
        #pragma unroll
        for (int k = 0; k < 2; k++) {
            sm[2304 + xi(lbase+k,co)] = aq[k];
            sm[4608 + xi(lbase+k,co)] = ak[k];
            sm[6912 + xi(lbase+k,co)] = av[k];
        }
    }
    __syncthreads();

    // phase 3: attention. thread = (h, l, quarter); m = 4*mm + quarter.
    {
        const int h = t >> 8, rem = t & 255;
        const int l = rem >> 2, quarter = rem & 3;
        const int hc = h*D_;
        const float rsd = 0.35355339059327373f;

        ulonglong2 qa = *reinterpret_cast<const ulonglong2*>(&sm[2304 + xi(l,hc)]);
        ulonglong2 qb = *reinterpret_cast<const ulonglong2*>(&sm[2304 + xi(l,hc+4)]);
        const u64 rsd2 = pack2(rsd, rsd);
        qa.x = mul2(qa.x, rsd2); qa.y = mul2(qa.y, rsd2);
        qb.x = mul2(qb.x, rsd2); qb.y = mul2(qb.y, rsd2);
        const float cw = conv_w[h], cb = conv_b[h];

        float Z = 0.f;
        u64 A0 = 0ull, A1 = 0ull, A2 = 0ull, A3 = 0ull;

        #pragma unroll 4
        for (int mm = 0; mm < 16; mm++) {
            const int m = mm*4 + quarter;
            const ulonglong2 ka = *reinterpret_cast<const ulonglong2*>(&sm[4608 + xi(m,hc)]);
            const ulonglong2 kb = *reinterpret_cast<const ulonglong2*>(&sm[4608 + xi(m,hc+4)]);
            u64 u = mul2(qa.x, ka.x);
            u = fma2(qa.y, ka.y, u);
            u = fma2(qb.x, kb.x, u);
            u = fma2(qb.y, kb.y, u);
            const float2 uf = unpack2(u);
            const float sc = uf.x + uf.y + fmaf(sm[BKI(l,m)], cw, cb);
            const float p = __expf(sc);
            Z += p;
            const u64 pp = pack2(p, p);
            const ulonglong2 va = *reinterpret_cast<const ulonglong2*>(&sm[6912 + xi(m,hc)]);
            const ulonglong2 vb = *reinterpret_cast<const ulonglong2*>(&sm[6912 + xi(m,hc+4)]);
            A0 = fma2(pp, va.x, A0); A1 = fma2(pp, va.y, A1);
            A2 = fma2(pp, vb.x, A2); A3 = fma2(pp, vb.y, A3);
        }
        #pragma unroll
        for (int o = 1; o < 4; o <<= 1) {
            Z  += __shfl_xor_sync(0xffffffffu, Z, o);
            A0 = add2(A0, __shfl_xor_sync(0xffffffffu, A0, o));
            A1 = add2(A1, __shfl_xor_sync(0xffffffffu, A1, o));
            A2 = add2(A2, __shfl_xor_sync(0xffffffffu, A2, o));
            A3 = add2(A3, __shfl_xor_sync(0xffffffffu, A3, o));
        }

        __syncthreads();
        if (quarter == 0) {
            const float inv = 1.f/Z;
            const float2 f0 = unpack2(A0), f1 = unpack2(A1), f2 = unpack2(A2), f3 = unpack2(A3);
            float o[D_];
            o[0]=f0.x*inv; o[1]=f0.y*inv; o[2]=f1.x*inv; o[3]=f1.y*inv;
            o[4]=f2.x*inv; o[5]=f2.y*inv; o[6]=f3.x*inv; o[7]=f3.y*inv;
            float4 r0, r1;
            float* rp = &r0.x;
            #pragma unroll
            for (int d = 0; d < D_; d++) {
                float g = sm[22146 + hc + d];
                #pragma unroll
                for (int dd = 0; dd < D_; dd++)
                    g += sm[21890 + h*D_*D_ + d*D_ + dd]*o[dd];
                ((d < 4) ? (&r0.x) : (&r1.x))[d & 3] = o[d] / (1.f + __expf(-g));
            }
            (void)rp;
            *reinterpret_cast<float4*>(&sm[2304 + xi(l,hc)])   = r0;
            *reinterpret_cast<float4*>(&sm[2304 + xi(l,hc+4)]) = r1;
        }
    }
    __syncthreads();

    // phase 4a: wo + residual -> KS
    {
        const int co = t & 31, lbase = (t >> 5) * 2;
        float acc[2];
        const float ib = bo[co];
        acc[0] = ib; acc[1] = ib;
        #pragma unroll 8
        for (int c = 0; c < C_; c++) {
            const float w = sm[12384 + co*33 + c];
            #pragma unroll
            for (int k = 0; k < 2; k++) acc[k] += sm[2304 + xi(lbase+k, c)]*w;
        }
        #pragma unroll
        for (int k = 0; k < 2; k++)
            sm[4608 + xi(lbase+k, co)] = sm[xi(lbase+k, co)] + acc[k];
    }
    __syncthreads();

    // phase 4b: LN(an) -> g_xbuf. 16 threads/row, 2 c each.
    {
        const int l = t >> 4, q = t & 15, c0 = q*2;
        const float v0 = sm[4608 + xi(l, c0)];
        const float v1 = sm[4608 + xi(l, c0+1)];
        float s1 = v0 + v1, s2 = v0*v0 + v1*v1;
        #pragma unroll
        for (int o = 1; o < 16; o <<= 1) {
            s1 += __shfl_xor_sync(0xffffffffu, s1, o);
            s2 += __shfl_xor_sync(0xffffffffu, s2, o);
        }
        const float mean = s1*(1.f/C_);
        const float rstd = rsqrtf(s2*(1.f/C_) - mean*mean + 1e-5f);
        float2 r;
        r.x = (v0-mean)*rstd*an_g[c0]   + an_b[c0];
        r.y = (v1-mean)*rstd*an_g[c0+1] + an_b[c0+1];
        *reinterpret_cast<float2*>(&g_xbuf[((b*S_ + s)*L_ + l)*C_ + c0]) = r;
    }
}

// ---------------------------------------------------------------------------
// Kernel W: fused max-over-tracks + wi projection + (p==0) m/nrm emission.
// ---------------------------------------------------------------------------
__global__ void __launch_bounds__(256) kW(const float* __restrict__ pp_w) {
    __shared__ float ms[L_][C_+1];
    __shared__ float pw[C_][C_+1];
    const int t = threadIdx.x;
    const int b = blockIdx.x >> 4, p = blockIdx.x & 15;
    const float* xb = g_xbuf + b*S_*L_*C_;

    for (int idx = t; idx < L_*C_; idx += 256) {
        float m = fmaxf(fmaxf(xb[idx], xb[2048+idx]),
                        fmaxf(xb[4096+idx], xb[6144+idx]));
        ms[idx>>5][idx&31] = m;
        if (p == 0) g_mbuf[b*L_*C_ + idx] = m;
    }
    for (int idx = t; idx < C_*C_; idx += 256)
        pw[idx>>5][idx&31] = pp_w[p*C_*C_ + idx];
    __syncthreads();

    if (p == 0 && t < L_) {
        float ssum = 0.f;
        #pragma unroll
        for (int c = 0; c < C_; c++) { const float v = ms[t][c]; ssum += v*v; }
        g_nrm[b*L_ + t] = sqrtf(ssum);
    }

    const int d = t & 31, ig = t >> 5;
    float acc[8];
    #pragma unroll
    for (int k = 0; k < 8; k++) acc[k] = 0.f;
    #pragma unroll 8
    for (int c = 0; c < C_; c++) {
        const float w = pw[c][d];
        #pragma unroll
        for (int k = 0; k < 8; k++) acc[k] += ms[ig*8+k][c]*w;
    }
    #pragma unroll
    for (int k = 0; k < 8; k++)
        g_wibuf[((b*L_ + ig*8+k)*CP_ + p)*C_ + d] = acc[k];
}

// ---------------------------------------------------------------------------
// Kernel B: grid = (b, i-pair), 256 threads. feat in registers, AdaNorm via
// shfl over the 8 pq threads, float4 stores.
// ---------------------------------------------------------------------------
__global__ void __launch_bounds__(256) kB(
    const float* __restrict__ pp_b,
    const float* __restrict__ ada_g, const float* __restrict__ ada_b,
    const float* __restrict__ ada_alpha, float* __restrict__ out)
{
    __shared__ float msB[64*36];
    __shared__ float wiB[2*16*36];
    __shared__ float nrmS[L_];

    const int t = threadIdx.x;
    const int b = blockIdx.x >> 5, i0 = (blockIdx.x & 31) * 2;

    for (int idx = t; idx < L_*C_; idx += 256)
        msB[swz(idx>>5, idx&31)] = g_mbuf[b*L_*C_ + idx];
    for (int idx = t; idx < 2*CP_*C_; idx += 256) {
        const int ii = idx >> 9, p = (idx >> 5) & 15, d = idx & 31;
        wiB[ii*576 + swz(p,d)] = g_wibuf[(b*L_ + i0)*CP_*C_ + idx];
    }
    if (t < L_) nrmS[t] = g_nrm[b*L_ + t];
    __syncthreads();

    const int ii = t >> 7, sub = t & 127;
    const int jg = sub >> 3, j0 = jg*4;
    const int pq = sub & 7;
    const int i = i0 + ii;

    u64 acc[2][4];
    #pragma unroll
    for (int pk = 0; pk < 2; pk++)
        #pragma unroll
        for (int jk = 0; jk < 4; jk++) acc[pk][jk] = 0ull;

    #pragma unroll
    for (int ch = 0; ch < 8; ch++) {
        const int cd = ch*4;
        ulonglong2 mj[4], wp[2];
        #pragma unroll
        for (int jk = 0; jk < 4; jk++)
            mj[jk] = *reinterpret_cast<const ulonglong2*>(&msB[swz(j0+jk, cd)]);
        #pragma unroll
        for (int pk = 0; pk < 2; pk++)
            wp[pk] = *reinterpret_cast<const ulonglong2*>(&wiB[ii*576 + swz(pq+8*pk, cd)]);
        #pragma unroll
        for (int pk = 0; pk < 2; pk++)
            #pragma unroll
            for (int jk = 0; jk < 4; jk++) {
                acc[pk][jk] = fma2(wp[pk].x, mj[jk].x, acc[pk][jk]);
                acc[pk][jk] = fma2(wp[pk].y, mj[jk].y, acc[pk][jk]);
            }
    }

    const float ni = nrmS[i];
    float invd[4];
    #pragma unroll
    for (int jk = 0; jk < 4; jk++)
        invd[jk] = __fdividef(1.f, fmaxf(ni*nrmS[j0+jk], 1e-6f));

    float feat[2][4];
    #pragma unroll
    for (int pk = 0; pk < 2; pk++) {
        const float bp = pp_b[pq + 8*pk];
        #pragma unroll
        for (int jk = 0; jk < 4; jk++) {
            const float2 f = unpack2(acc[pk][jk]);
            feat[pk][jk] = (f.x + f.y)*invd[jk] + bp;
        }
    }

    float s1[4], s2[4];
    #pragma unroll
    for (int jk = 0; jk < 4; jk++) {
        s1[jk] = feat[0][jk] + feat[1][jk];
        s2[jk] = feat[0][jk]*feat[0][jk] + feat[1][jk]*feat[1][jk];
    }
    #pragma unroll
    for (int o = 1; o < 8; o <<= 1) {
        #pragma unroll
        for (int jk = 0; jk < 4; jk++) {
            s1[jk] += __shfl_xor_sync(0xffffffffu, s1[jk], o);
            s2[jk] += __shfl_xor_sync(0xffffffffu, s2[jk], o);
        }
    }
    float mu[4], rsd[4];
    #pragma unroll
    for (int jk = 0; jk < 4; jk++) {
        mu[jk] = s1[jk]*(1.f/CP_);
        rsd[jk] = rsqrtf(s2[jk]*(1.f/CP_) - mu[jk]*mu[jk] + 1e-5f);
    }

    const float alpha = ada_alpha[0];
    #pragma unroll
    for (int pk = 0; pk < 2; pk++) {
        const int p = pq + 8*pk;
        const float g = ada_g[p], bb = ada_b[p];
        float4 r;
        float* rp = &r.x;
        #pragma unroll
        for (int jk = 0; jk < 4; jk++) {
            const float v = feat[pk][jk];
            const float ln = (v - mu[jk])*rsd[jk]*g + bb;
            const float val = v + alpha*ln;
            rp[jk] = __fdividef(val, 1.f + __expf(-val));
        }
        *reinterpret_cast<float4*>(&out[((b*CP_ + p)*L_ + i)*L_ + j0]) = r;
    }
}

extern "C" void kernel_launch(void* const* d_in, const int* in_sizes, int n_in,
                              void* d_out, int out_size) {
    const float* in[29];
    for (int i = 0; i < 29 && i < n_in; i++) in[i] = (const float*)d_in[i];

    cudaFuncSetAttribute(kA, cudaFuncAttributeMaxDynamicSharedMemorySize, KA_SMEM);

    kA<<<B_*S_, 1024, KA_SMEM>>>(in[0], in[1], in[2], in[3], in[4],
                                 in[5], in[6], in[7], in[8], in[9],
                                 in[10], in[11], in[12], in[13], in[14], in[15],
                                 in[16], in[17], in[18], in[19],
                                 in[20], in[21], in[22], in[23]);
    kW<<<B_*CP_, 256>>>(in[24]);
    kB<<<B_*L_/2, 256>>>(in[25], in[26], in[27], in[28], (float*)d_out);
}